// round 7
// baseline (speedup 1.0000x reference)
#include <cuda_runtime.h>
#include <cuda_bf16.h>
#include <cstdint>

#define T_DIM    168
#define C_DIM    1024
#define NSEQ     168
#define HORIZON  24
#define KPAD     176                 // 11 k-steps of 16
#define KSTEPS   11

// ---- smem layout ----
#define ROW_F       132              // floats per padded row (528 B)
#define STAGE_BYTES (16 * 528)       // 8448 per chunk buffer
#define NBUF        3
#define BFRAG_OFF   (NBUF * STAGE_BYTES)       // 25344
#define BFRAG_U32   (2 * KSTEPS * 3 * 64)      // 4224 u32 = 16896 B
#define SMEM_BYTES  (BFRAG_OFF + BFRAG_U32 * 4)  // 42240 (< 48K, no attr needed)

__device__ __align__(16) uint32_t g_Bfrag[BFRAG_U32];
__device__ float g_beta[HORIZON];

// =================== kernel 0: Meff -> pre-arranged B fragments ===================
__global__ void precompute_kernel(const float* __restrict__ w,
                                  const float* __restrict__ bias) {
    __shared__ float Msm[HORIZON][KPAD];
    __shared__ float ws[NSEQ];
    const int tid = threadIdx.x;                    // 256 threads
    if (tid < NSEQ) ws[tid] = w[tid];
    __syncthreads();

    if (tid < KPAD) {
        const int t = tid;
        float col[HORIZON];
#pragma unroll
        for (int h = 0; h < HORIZON; ++h) {
            int n = t - h;
            float acc = (n >= 0 && n < NSEQ) ? ws[n] : 0.f;
            for (int j = 0; j < h; ++j) acc += ws[NSEQ - h + j] * col[j];
            col[h] = acc;
            Msm[h][t] = acc;
        }
    }
    if (tid == 0) {
        float bb[HORIZON];
        float bv = bias[0];
        for (int h = 0; h < HORIZON; ++h) {
            float acc = bv;
            for (int j = 0; j < h; ++j) acc += ws[NSEQ - h + j] * bb[j];
            bb[h] = acc;
            g_beta[h] = acc;
        }
    }
    __syncthreads();

    // fragment layout: idx = ((s*11 + kt)*3 + nt)*64 + lane*2 + r
    // value = bf16x2 { upper: split(M[n][k0+1]), lower: split(M[n][k0]) }
    // k0 = kt*16 + (lane%4)*2 + r*8 ; n = nt*8 + lane/4 ; s: 0=hi, 1=lo
    for (int idx = tid; idx < BFRAG_U32; idx += 256) {
        int r    = idx & 1;
        int lane = (idx >> 1) & 31;
        int rest = idx >> 6;
        int nt   = rest % 3;
        int kt   = (rest / 3) % KSTEPS;
        int s    = rest / (3 * KSTEPS);
        int k0   = kt * 16 + (lane & 3) * 2 + r * 8;
        int n    = nt * 8 + (lane >> 2);
        float v0 = Msm[n][k0], v1 = Msm[n][k0 + 1];
        __nv_bfloat16 h0 = __float2bfloat16(v0);
        __nv_bfloat16 h1 = __float2bfloat16(v1);
        __nv_bfloat16 e0, e1;
        if (s == 0) { e0 = h0; e1 = h1; }
        else {
            e0 = __float2bfloat16(v0 - __bfloat162float(h0));
            e1 = __float2bfloat16(v1 - __bfloat162float(h1));
        }
        unsigned short b0 = *reinterpret_cast<unsigned short*>(&e0);
        unsigned short b1 = *reinterpret_cast<unsigned short*>(&e1);
        g_Bfrag[idx] = ((uint32_t)b1 << 16) | (uint32_t)b0;
    }
}

// =================== PTX helpers ===================
__device__ __forceinline__ void cp16(uint32_t saddr, const void* gptr) {
    asm volatile("cp.async.cg.shared.global [%0], [%1], 16;"
                 :: "r"(saddr), "l"(gptr));
}
__device__ __forceinline__ void cp_commit() {
    asm volatile("cp.async.commit_group;");
}
template<int N>
__device__ __forceinline__ void cp_wait() {
    asm volatile("cp.async.wait_group %0;" :: "n"(N) : "memory");
}
__device__ __forceinline__ uint32_t cvt2(float hi, float lo) {
    uint32_t r;
    asm("cvt.rn.bf16x2.f32 %0, %1, %2;" : "=r"(r) : "f"(hi), "f"(lo));
    return r;
}
// split packed pair: hp = bf16x2(v1,v0), lp = bf16x2 of residuals
__device__ __forceinline__ void split_pair(float v0, float v1,
                                           uint32_t& hp, uint32_t& lp) {
    hp = cvt2(v1, v0);
    float h1 = __uint_as_float(hp & 0xffff0000u);
    float h0 = __uint_as_float(hp << 16);
    lp = cvt2(v1 - h1, v0 - h0);
}
__device__ __forceinline__ void mma16816(float* c, const uint32_t* a,
                                         const uint32_t* b) {
    asm volatile(
        "mma.sync.aligned.m16n8k16.row.col.f32.bf16.bf16.f32 "
        "{%0,%1,%2,%3}, {%4,%5,%6,%7}, {%8,%9}, {%0,%1,%2,%3};"
        : "+f"(c[0]), "+f"(c[1]), "+f"(c[2]), "+f"(c[3])
        : "r"(a[0]), "r"(a[1]), "r"(a[2]), "r"(a[3]), "r"(b[0]), "r"(b[1]));
}
__device__ __forceinline__ void lds_v2(uint32_t& r0, uint32_t& r1, uint32_t addr) {
    asm volatile("ld.shared.v2.u32 {%0,%1}, [%2];"
                 : "=r"(r0), "=r"(r1) : "r"(addr));
}

// =================== main kernel ===================
// CTA = 128 channels of one b (grid 8 x 256), 4 warps; warp owns 32 channels.
// D[128 x 24] = Y[128 x 176] * Meff^T[176 x 24] via mma.sync bf16 3-pass split.
__global__ __launch_bounds__(128, 4)
void ar_mma_kernel(const float* __restrict__ y, float* __restrict__ out) {
    extern __shared__ char sm[];
    const int tid   = threadIdx.x;
    const int wid   = tid >> 5;
    const int lane  = tid & 31;
    const int lane4 = lane & 3;
    const int laneg = lane >> 2;
    const uint32_t sb = (uint32_t)__cvta_generic_to_shared((void*)sm);

    const int b  = blockIdx.y;
    const int c0 = blockIdx.x * 128;
    const char* ytile = (const char*)(y + ((long long)b * T_DIM) * C_DIM + c0);

    // 16-row chunk prefetch: 512 B rows -> 528 B padded smem rows
    auto prefetch = [&](int ch) {
        const int nrows = (ch == 10) ? 8 : 16;       // chunk 10: t 160..167 only
        const uint32_t sdst = sb + (ch % NBUF) * STAGE_BYTES;
        const char*    gsrc = ytile + (long long)ch * 16 * 4096;
#pragma unroll
        for (int j = 0; j < 4; ++j) {
            int id  = j * 128 + tid;
            int row = id >> 5;
            int col = (id & 31) << 4;
            if (row < nrows)
                cp16(sdst + row * 528 + col, gsrc + (long long)row * 4096 + col);
        }
    };

    // B fragments (16896 B) + chunk 0 in group 0; chunk 1 in group 1
#pragma unroll
    for (int j = 0; j < 9; ++j) {
        int id = j * 128 + tid;
        if (id < BFRAG_U32 / 4)
            cp16(sb + BFRAG_OFF + id * 16, (const char*)g_Bfrag + id * 16);
    }
    prefetch(0); cp_commit();
    prefetch(1); cp_commit();

    float acc[2][3][4];
#pragma unroll
    for (int m = 0; m < 2; ++m)
#pragma unroll
        for (int n = 0; n < 3; ++n)
#pragma unroll
            for (int r = 0; r < 4; ++r) acc[m][n][r] = 0.f;

    const int t0 = lane4 * 2;

#pragma unroll 1
    for (int kt = 0; kt < KSTEPS; ++kt) {
        if (kt < KSTEPS - 1) { cp_wait<1>(); } else { cp_wait<0>(); }
        __syncthreads();
        if (kt + 2 < KSTEPS) { prefetch(kt + 2); cp_commit(); }

        // B fragments for this k-step: one LDS.64 each
        uint32_t Bh[3][2], Bl[3][2];
#pragma unroll
        for (int nt = 0; nt < 3; ++nt) {
            lds_v2(Bh[nt][0], Bh[nt][1],
                   sb + BFRAG_OFF + (uint32_t)(((0 * KSTEPS + kt) * 3 + nt) * 256 + lane * 8));
            lds_v2(Bl[nt][0], Bl[nt][1],
                   sb + BFRAG_OFF + (uint32_t)(((1 * KSTEPS + kt) * 3 + nt) * 256 + lane * 8));
        }

        const float* stg = (const float*)(sm + (kt % NBUF) * STAGE_BYTES);
        const bool full = (kt < KSTEPS - 1);

#pragma unroll
        for (int m = 0; m < 2; ++m) {
            const int chI = wid * 32 + m * 16 + laneg;
            const float* p = stg + chI;

            float w00 = p[t0 * ROW_F],       w01 = p[(t0 + 1) * ROW_F];
            float w10 = p[t0 * ROW_F + 8],   w11 = p[(t0 + 1) * ROW_F + 8];

            uint32_t Ah[4], Al[4];
            split_pair(w00, w01, Ah[0], Al[0]);
            split_pair(w10, w11, Ah[1], Al[1]);
            if (full) {
                float w02 = p[(t0 + 8) * ROW_F],     w03 = p[(t0 + 9) * ROW_F];
                float w12 = p[(t0 + 8) * ROW_F + 8], w13 = p[(t0 + 9) * ROW_F + 8];
                split_pair(w02, w03, Ah[2], Al[2]);
                split_pair(w12, w13, Ah[3], Al[3]);
            } else {
                Ah[2] = Ah[3] = Al[2] = Al[3] = 0u;   // t >= 168 contributes 0
            }

#pragma unroll
            for (int nt = 0; nt < 3; ++nt) {
                mma16816(acc[m][nt], Ah, Bh[nt]);     // Ah*Bh
                mma16816(acc[m][nt], Al, Bh[nt]);     // Al*Bh
                mma16816(acc[m][nt], Ah, Bl[nt]);     // Ah*Bl
            }
        }
    }

    // ---- epilogue: add beta, store out[b, h, c] ----
    float* ob = out + (long long)b * HORIZON * C_DIM + c0;
#pragma unroll
    for (int nt = 0; nt < 3; ++nt) {
        const int h0 = nt * 8 + lane4 * 2;
        const float be0 = __ldg(&g_beta[h0]);
        const float be1 = __ldg(&g_beta[h0 + 1]);
#pragma unroll
        for (int m = 0; m < 2; ++m) {
            const int row = wid * 32 + m * 16 + laneg;
            ob[(long long)h0 * C_DIM + row]           = acc[m][nt][0] + be0;
            ob[(long long)(h0 + 1) * C_DIM + row]     = acc[m][nt][1] + be1;
            ob[(long long)h0 * C_DIM + row + 8]       = acc[m][nt][2] + be0;
            ob[(long long)(h0 + 1) * C_DIM + row + 8] = acc[m][nt][3] + be1;
        }
    }
}

extern "C" void kernel_launch(void* const* d_in, const int* in_sizes, int n_in,
                              void* d_out, int out_size) {
    // metadata order: x (unused), y, w, b
    const float* y    = (const float*)d_in[1];
    const float* w    = (const float*)d_in[2];
    const float* bias = (const float*)d_in[3];
    float* out        = (float*)d_out;

    precompute_kernel<<<1, 256>>>(w, bias);
    dim3 grid(C_DIM / 128, 256);
    ar_mma_kernel<<<grid, 128, SMEM_BYTES>>>(y, out);
}

// round 8
// speedup vs baseline: 1.0462x; 1.0462x over previous
#include <cuda_runtime.h>
#include <cuda_bf16.h>
#include <cstdint>

#define T_DIM    168
#define C_DIM    1024
#define NSEQ     168
#define HORIZON  24
#define KPAD     176                 // 11 k-steps of 16
#define KSTEPS   11

// ---- smem layout ----
#define ROW_F       132              // floats per padded row (528 B)
#define STAGE_BYTES (16 * 528)       // 8448 per chunk buffer
#define NBUF        3
#define BFRAG_OFF   (NBUF * STAGE_BYTES)       // 25344
#define BFRAG_U32   (2 * KSTEPS * 3 * 64)      // 4224 u32 = 16896 B
#define SBETA_OFF   (BFRAG_OFF + BFRAG_U32 * 4)     // 42240
#define SMEM_BYTES  (SBETA_OFF + HORIZON * 4)       // 42336 (< 48K)

// transient overlays (phase 0 only, before any prefetch):
//   Msm[24][176] fp32 at offset 0        (16896 B = stage buffers 0..1)
//   ws[168]      fp32 at offset 16896    (inside stage buffer 2)
#define WS_OFF      (2 * STAGE_BYTES)

// =================== PTX helpers ===================
__device__ __forceinline__ void cp16(uint32_t saddr, const void* gptr) {
    asm volatile("cp.async.cg.shared.global [%0], [%1], 16;"
                 :: "r"(saddr), "l"(gptr));
}
__device__ __forceinline__ void cp_commit() {
    asm volatile("cp.async.commit_group;");
}
template<int N>
__device__ __forceinline__ void cp_wait() {
    asm volatile("cp.async.wait_group %0;" :: "n"(N) : "memory");
}
__device__ __forceinline__ uint32_t cvt2(float hi, float lo) {
    uint32_t r;
    asm("cvt.rn.bf16x2.f32 %0, %1, %2;" : "=r"(r) : "f"(hi), "f"(lo));
    return r;
}
// split packed pair: hp = bf16x2(v1,v0), lp = bf16x2 of residuals
__device__ __forceinline__ void split_pair(float v0, float v1,
                                           uint32_t& hp, uint32_t& lp) {
    hp = cvt2(v1, v0);
    float h1 = __uint_as_float(hp & 0xffff0000u);
    float h0 = __uint_as_float(hp << 16);
    lp = cvt2(v1 - h1, v0 - h0);
}
__device__ __forceinline__ void mma16816(float* c, const uint32_t* a,
                                         const uint32_t* b) {
    asm volatile(
        "mma.sync.aligned.m16n8k16.row.col.f32.bf16.bf16.f32 "
        "{%0,%1,%2,%3}, {%4,%5,%6,%7}, {%8,%9}, {%0,%1,%2,%3};"
        : "+f"(c[0]), "+f"(c[1]), "+f"(c[2]), "+f"(c[3])
        : "r"(a[0]), "r"(a[1]), "r"(a[2]), "r"(a[3]), "r"(b[0]), "r"(b[1]));
}
__device__ __forceinline__ void lds_v2(uint32_t& r0, uint32_t& r1, uint32_t addr) {
    asm volatile("ld.shared.v2.u32 {%0,%1}, [%2];"
                 : "=r"(r0), "=r"(r1) : "r"(addr));
}

// =================== fused kernel ===================
// CTA = 128 channels of one b (grid 8 x 256), 4 warps.
// Phase 0 (per CTA, ~1.2us): unroll the AR recursion into Meff[24][176] and
// beta[24]; pack Meff bf16 hi/lo mma fragments straight into SMEM.
// Phase 1: D[128 x 24] = Y[128 x 176] * Meff^T via mma.sync bf16 3-pass split,
// streaming y through a 3-buffer cp.async pipeline. (identical to R7 loop)
__global__ __launch_bounds__(128, 4)
void ar_mma_kernel(const float* __restrict__ y,
                   const float* __restrict__ w,
                   const float* __restrict__ bias,
                   float* __restrict__ out) {
    extern __shared__ char sm[];
    const int tid   = threadIdx.x;
    const int wid   = tid >> 5;
    const int lane  = tid & 31;
    const int lane4 = lane & 3;
    const int laneg = lane >> 2;
    const uint32_t sb = (uint32_t)__cvta_generic_to_shared((void*)sm);

    float* Msm   = (float*)sm;                       // [24][176], transient
    float* ws    = (float*)(sm + WS_OFF);            // [168],      transient
    uint32_t* bf = (uint32_t*)(sm + BFRAG_OFF);      // fragments, persistent
    float* sbeta = (float*)(sm + SBETA_OFF);         // [24],       persistent

    // ---- phase 0a: w into smem ----
    for (int i = tid; i < NSEQ; i += 128) ws[i] = w[i];
    __syncthreads();

    // ---- phase 0b: unrolled-recursion columns Meff[:, t] ----
    for (int t = tid; t < KPAD; t += 128) {
        float col[HORIZON];
#pragma unroll
        for (int h = 0; h < HORIZON; ++h) {
            int n = t - h;
            float acc = (n >= 0 && n < NSEQ) ? ws[n] : 0.f;
            for (int j = 0; j < h; ++j) acc += ws[NSEQ - h + j] * col[j];
            col[h] = acc;
            Msm[h * KPAD + t] = acc;
        }
    }
    // beta (serial 24-step recursion, one thread)
    if (tid == 127) {
        float bb[HORIZON];
        float bv = bias[0];
#pragma unroll
        for (int h = 0; h < HORIZON; ++h) {
            float acc = bv;
            for (int j = 0; j < h; ++j) acc += ws[NSEQ - h + j] * bb[j];
            bb[h] = acc;
            sbeta[h] = acc;
        }
    }
    __syncthreads();

    // ---- phase 0c: pack mma B fragments (bf16 hi/lo) into smem ----
    // idx = ((s*11 + kt)*3 + nt)*64 + lane*2 + r
    // k0 = kt*16 + (lane%4)*2 + r*8 ; n = nt*8 + lane/4 ; s: 0=hi, 1=lo
    for (int idx = tid; idx < BFRAG_U32; idx += 128) {
        int r    = idx & 1;
        int ln   = (idx >> 1) & 31;
        int rest = idx >> 6;
        int nt   = rest % 3;
        int kt   = (rest / 3) % KSTEPS;
        int s    = rest / (3 * KSTEPS);
        int k0   = kt * 16 + (ln & 3) * 2 + r * 8;
        int n    = nt * 8 + (ln >> 2);
        float v0 = Msm[n * KPAD + k0], v1 = Msm[n * KPAD + k0 + 1];
        uint32_t hp, lp;
        split_pair(v0, v1, hp, lp);
        bf[idx] = s ? lp : hp;
    }
    __syncthreads();                  // Msm dead; stage buffers reusable

    // ================= phase 1: streaming GEMM (R7 loop, unchanged) =========
    const int b  = blockIdx.y;
    const int c0 = blockIdx.x * 128;
    const char* ytile = (const char*)(y + ((long long)b * T_DIM) * C_DIM + c0);

    auto prefetch = [&](int ch) {
        const int nrows = (ch == 10) ? 8 : 16;       // chunk 10: t 160..167 only
        const uint32_t sdst = sb + (ch % NBUF) * STAGE_BYTES;
        const char*    gsrc = ytile + (long long)ch * 16 * 4096;
#pragma unroll
        for (int j = 0; j < 4; ++j) {
            int id  = j * 128 + tid;
            int row = id >> 5;
            int col = (id & 31) << 4;
            if (row < nrows)
                cp16(sdst + row * 528 + col, gsrc + (long long)row * 4096 + col);
        }
    };

    prefetch(0); cp_commit();
    prefetch(1); cp_commit();

    float acc[2][3][4];
#pragma unroll
    for (int m = 0; m < 2; ++m)
#pragma unroll
        for (int n = 0; n < 3; ++n)
#pragma unroll
            for (int r = 0; r < 4; ++r) acc[m][n][r] = 0.f;

    const int t0 = lane4 * 2;

#pragma unroll 1
    for (int kt = 0; kt < KSTEPS; ++kt) {
        if (kt < KSTEPS - 1) { cp_wait<1>(); } else { cp_wait<0>(); }
        __syncthreads();
        if (kt + 2 < KSTEPS) { prefetch(kt + 2); cp_commit(); }

        uint32_t Bh[3][2], Bl[3][2];
#pragma unroll
        for (int nt = 0; nt < 3; ++nt) {
            lds_v2(Bh[nt][0], Bh[nt][1],
                   sb + BFRAG_OFF + (uint32_t)(((0 * KSTEPS + kt) * 3 + nt) * 256 + lane * 8));
            lds_v2(Bl[nt][0], Bl[nt][1],
                   sb + BFRAG_OFF + (uint32_t)(((1 * KSTEPS + kt) * 3 + nt) * 256 + lane * 8));
        }

        const float* stg = (const float*)(sm + (kt % NBUF) * STAGE_BYTES);
        const bool full = (kt < KSTEPS - 1);

#pragma unroll
        for (int m = 0; m < 2; ++m) {
            const int chI = wid * 32 + m * 16 + laneg;
            const float* p = stg + chI;

            float w00 = p[t0 * ROW_F],       w01 = p[(t0 + 1) * ROW_F];
            float w10 = p[t0 * ROW_F + 8],   w11 = p[(t0 + 1) * ROW_F + 8];

            uint32_t Ah[4], Al[4];
            split_pair(w00, w01, Ah[0], Al[0]);
            split_pair(w10, w11, Ah[1], Al[1]);
            if (full) {
                float w02 = p[(t0 + 8) * ROW_F],     w03 = p[(t0 + 9) * ROW_F];
                float w12 = p[(t0 + 8) * ROW_F + 8], w13 = p[(t0 + 9) * ROW_F + 8];
                split_pair(w02, w03, Ah[2], Al[2]);
                split_pair(w12, w13, Ah[3], Al[3]);
            } else {
                Ah[2] = Ah[3] = Al[2] = Al[3] = 0u;   // t >= 168 contributes 0
            }

#pragma unroll
            for (int nt = 0; nt < 3; ++nt) {
                mma16816(acc[m][nt], Ah, Bh[nt]);     // Ah*Bh
                mma16816(acc[m][nt], Al, Bh[nt]);     // Al*Bh
                mma16816(acc[m][nt], Ah, Bl[nt]);     // Ah*Bl
            }
        }
    }

    // ---- epilogue: add beta, store out[b, h, c] ----
    float* ob = out + (long long)b * HORIZON * C_DIM + c0;
#pragma unroll
    for (int nt = 0; nt < 3; ++nt) {
        const int h0 = nt * 8 + lane4 * 2;
        const float be0 = sbeta[h0];
        const float be1 = sbeta[h0 + 1];
#pragma unroll
        for (int m = 0; m < 2; ++m) {
            const int row = wid * 32 + m * 16 + laneg;
            ob[(long long)h0 * C_DIM + row]           = acc[m][nt][0] + be0;
            ob[(long long)(h0 + 1) * C_DIM + row]     = acc[m][nt][1] + be1;
            ob[(long long)h0 * C_DIM + row + 8]       = acc[m][nt][2] + be0;
            ob[(long long)(h0 + 1) * C_DIM + row + 8] = acc[m][nt][3] + be1;
        }
    }
}

extern "C" void kernel_launch(void* const* d_in, const int* in_sizes, int n_in,
                              void* d_out, int out_size) {
    // metadata order: x (unused), y, w, b
    const float* y    = (const float*)d_in[1];
    const float* w    = (const float*)d_in[2];
    const float* bias = (const float*)d_in[3];
    float* out        = (float*)d_out;

    dim3 grid(C_DIM / 128, 256);
    ar_mma_kernel<<<grid, 128, SMEM_BYTES>>>(y, w, bias, out);
}

// round 9
// speedup vs baseline: 1.0520x; 1.0056x over previous
#include <cuda_runtime.h>
#include <cuda_bf16.h>
#include <cstdint>

#define T_DIM    168
#define C_DIM    1024
#define NSEQ     168
#define HORIZON  24
#define KPAD     176                 // 11 k-steps of 16
#define KSTEPS   11

// ---- smem layout ----
#define ROW_F       132              // floats per padded row (528 B)
#define STAGE_BYTES (16 * 528)       // 8448 per chunk buffer
#define NBUF        3
#define BFRAG_OFF   (NBUF * STAGE_BYTES)       // 25344
#define BFRAG_U32   (2 * KSTEPS * 3 * 64)      // 4224 u32 = 16896 B
#define SBETA_OFF   (BFRAG_OFF + BFRAG_U32 * 4)     // 42240
#define SMEM_BYTES  (SBETA_OFF + HORIZON * 4)       // 42336 (< 48K)

// =================== PTX helpers ===================
__device__ __forceinline__ void cp16(uint32_t saddr, const void* gptr) {
    asm volatile("cp.async.cg.shared.global [%0], [%1], 16;"
                 :: "r"(saddr), "l"(gptr));
}
__device__ __forceinline__ void cp_commit() {
    asm volatile("cp.async.commit_group;");
}
template<int N>
__device__ __forceinline__ void cp_wait() {
    asm volatile("cp.async.wait_group %0;" :: "n"(N) : "memory");
}
__device__ __forceinline__ uint32_t cvt2(float hi, float lo) {
    uint32_t r;
    asm("cvt.rn.bf16x2.f32 %0, %1, %2;" : "=r"(r) : "f"(hi), "f"(lo));
    return r;
}
// split packed pair: hp = bf16x2(v1,v0), lp = bf16x2 of residuals
__device__ __forceinline__ void split_pair(float v0, float v1,
                                           uint32_t& hp, uint32_t& lp) {
    hp = cvt2(v1, v0);
    float h1 = __uint_as_float(hp & 0xffff0000u);
    float h0 = __uint_as_float(hp << 16);
    lp = cvt2(v1 - h1, v0 - h0);
}
__device__ __forceinline__ void mma16816(float* c, const uint32_t* a,
                                         const uint32_t* b) {
    asm volatile(
        "mma.sync.aligned.m16n8k16.row.col.f32.bf16.bf16.f32 "
        "{%0,%1,%2,%3}, {%4,%5,%6,%7}, {%8,%9}, {%0,%1,%2,%3};"
        : "+f"(c[0]), "+f"(c[1]), "+f"(c[2]), "+f"(c[3])
        : "r"(a[0]), "r"(a[1]), "r"(a[2]), "r"(a[3]), "r"(b[0]), "r"(b[1]));
}
__device__ __forceinline__ void lds_v2(uint32_t& r0, uint32_t& r1, uint32_t addr) {
    asm volatile("ld.shared.v2.u32 {%0,%1}, [%2];"
                 : "=r"(r0), "=r"(r1) : "r"(addr));
}

// =================== fused kernel ===================
// CTA = 128 channels of one b (grid 8 x 256), 4 warps.
// Phase 0 (~0.4us/CTA, overlapped with the initial cp.async fill): unroll the
// AR recursion column-by-column in registers and scatter bf16 hi/lo mma
// fragments straight into SMEM via shfl pairing (no div/mod, no Msm).
// Phase 1: D[128 x 24] = Y[128 x 176] * Meff^T via mma.sync bf16 3-pass split
// (byte-identical to the 35.7us R7 loop).
__global__ __launch_bounds__(128, 4)
void ar_mma_kernel(const float* __restrict__ y,
                   const float* __restrict__ w,
                   const float* __restrict__ bias,
                   float* __restrict__ out) {
    extern __shared__ char sm[];
    const int tid   = threadIdx.x;
    const int wid   = tid >> 5;
    const int lane  = tid & 31;
    const int lane4 = lane & 3;
    const int laneg = lane >> 2;
    const uint32_t sb = (uint32_t)__cvta_generic_to_shared((void*)sm);

    uint32_t* bf = (uint32_t*)(sm + BFRAG_OFF);      // fragments
    float* sbeta = (float*)(sm + SBETA_OFF);         // [24]

    const int b  = blockIdx.y;
    const int c0 = blockIdx.x * 128;
    const char* ytile = (const char*)(y + ((long long)b * T_DIM) * C_DIM + c0);

    auto prefetch = [&](int ch) {
        const int nrows = (ch == 10) ? 8 : 16;       // chunk 10: t 160..167 only
        const uint32_t sdst = sb + (ch % NBUF) * STAGE_BYTES;
        const char*    gsrc = ytile + (long long)ch * 16 * 4096;
#pragma unroll
        for (int j = 0; j < 4; ++j) {
            int id  = j * 128 + tid;
            int row = id >> 5;
            int col = (id & 31) << 4;
            if (row < nrows)
                cp16(sdst + row * 528 + col, gsrc + (long long)row * 4096 + col);
        }
    };

    // ---- kick DRAM first: phase 0 hides under this fill ----
    prefetch(0); cp_commit();
    prefetch(1); cp_commit();

    // ================= phase 0: recursion -> fragments =================
    // w tail (w[144..167]) in registers; identical across threads (L1/const hot)
    float wt[HORIZON];
#pragma unroll
    for (int j = 0; j < HORIZON; ++j) wt[j] = __ldg(&w[144 + j]);

    // column t of Meff: col[h] = w[t-h] (if 0<=t-h<168) + sum_j wt[24-h+j]*col[j]
    // fragment scatter: pair (t even, t+1) via shfl_xor(1)
    // idx(s,kt,nt,ln,r) = ((s*11+kt)*3+nt)*64 + ln*2 + r
    // kt=t>>4, r=(t>>3)&1, ln4=(t&7)>>1, nt=h>>3, ln=(h&7)*4+ln4
#pragma unroll
    for (int pass = 0; pass < 2; ++pass) {
        if (pass == 1 && tid >= 64) break;           // warps 2,3 skip pass 2
        const int t  = tid + pass * 128;
        const bool wr = (t < KPAD) && ((t & 1) == 0);
        const int kt  = t >> 4;
        const int r   = (t >> 3) & 1;
        const int ln4 = (t & 7) >> 1;
        float col[HORIZON];
#pragma unroll
        for (int h = 0; h < HORIZON; ++h) {
            int n = t - h;
            float acc = (n >= 0 && n < NSEQ) ? __ldg(&w[n]) : 0.f;
#pragma unroll
            for (int j = 0; j < h; ++j) acc += wt[24 - h + j] * col[j];
            col[h] = acc;
            float v1 = __shfl_xor_sync(0xffffffffu, acc, 1);
            if (wr) {
                uint32_t hp, lp;
                split_pair(acc, v1, hp, lp);
                int base = (kt * 3 + (h >> 3)) * 64 + ((h & 7) * 4 + ln4) * 2 + r;
                bf[base] = hp;
                bf[KSTEPS * 3 * 64 + base] = lp;
            }
        }
    }
    // beta recursion (one thread in warp 3, concurrent with pass 2)
    if (tid == 127) {
        float bb[HORIZON];
        float bv = __ldg(&bias[0]);
#pragma unroll
        for (int h = 0; h < HORIZON; ++h) {
            float acc = bv;
#pragma unroll
            for (int j = 0; j < h; ++j) acc += wt[24 - h + j] * bb[j];
            bb[h] = acc;
            sbeta[h] = acc;
        }
    }
    __syncthreads();                      // fragments + beta visible

    // ================= phase 1: streaming GEMM (unchanged) =================
    float acc[2][3][4];
#pragma unroll
    for (int m = 0; m < 2; ++m)
#pragma unroll
        for (int n = 0; n < 3; ++n)
#pragma unroll
            for (int rr = 0; rr < 4; ++rr) acc[m][n][rr] = 0.f;

    const int t0 = lane4 * 2;

#pragma unroll 1
    for (int kt = 0; kt < KSTEPS; ++kt) {
        if (kt < KSTEPS - 1) { cp_wait<1>(); } else { cp_wait<0>(); }
        __syncthreads();
        if (kt + 2 < KSTEPS) { prefetch(kt + 2); cp_commit(); }

        uint32_t Bh[3][2], Bl[3][2];
#pragma unroll
        for (int nt = 0; nt < 3; ++nt) {
            lds_v2(Bh[nt][0], Bh[nt][1],
                   sb + BFRAG_OFF + (uint32_t)(((0 * KSTEPS + kt) * 3 + nt) * 256 + lane * 8));
            lds_v2(Bl[nt][0], Bl[nt][1],
                   sb + BFRAG_OFF + (uint32_t)(((1 * KSTEPS + kt) * 3 + nt) * 256 + lane * 8));
        }

        const float* stg = (const float*)(sm + (kt % NBUF) * STAGE_BYTES);
        const bool full = (kt < KSTEPS - 1);

#pragma unroll
        for (int m = 0; m < 2; ++m) {
            const int chI = wid * 32 + m * 16 + laneg;
            const float* p = stg + chI;

            float w00 = p[t0 * ROW_F],       w01 = p[(t0 + 1) * ROW_F];
            float w10 = p[t0 * ROW_F + 8],   w11 = p[(t0 + 1) * ROW_F + 8];

            uint32_t Ah[4], Al[4];
            split_pair(w00, w01, Ah[0], Al[0]);
            split_pair(w10, w11, Ah[1], Al[1]);
            if (full) {
                float w02 = p[(t0 + 8) * ROW_F],     w03 = p[(t0 + 9) * ROW_F];
                float w12 = p[(t0 + 8) * ROW_F + 8], w13 = p[(t0 + 9) * ROW_F + 8];
                split_pair(w02, w03, Ah[2], Al[2]);
                split_pair(w12, w13, Ah[3], Al[3]);
            } else {
                Ah[2] = Ah[3] = Al[2] = Al[3] = 0u;   // t >= 168 contributes 0
            }

#pragma unroll
            for (int nt = 0; nt < 3; ++nt) {
                mma16816(acc[m][nt], Ah, Bh[nt]);     // Ah*Bh
                mma16816(acc[m][nt], Al, Bh[nt]);     // Al*Bh
                mma16816(acc[m][nt], Ah, Bl[nt]);     // Ah*Bl
            }
        }
    }

    // ---- epilogue: add beta, store out[b, h, c] ----
    float* ob = out + (long long)b * HORIZON * C_DIM + c0;
#pragma unroll
    for (int nt = 0; nt < 3; ++nt) {
        const int h0 = nt * 8 + lane4 * 2;
        const float be0 = sbeta[h0];
        const float be1 = sbeta[h0 + 1];
#pragma unroll
        for (int m = 0; m < 2; ++m) {
            const int row = wid * 32 + m * 16 + laneg;
            ob[(long long)h0 * C_DIM + row]           = acc[m][nt][0] + be0;
            ob[(long long)(h0 + 1) * C_DIM + row]     = acc[m][nt][1] + be1;
            ob[(long long)h0 * C_DIM + row + 8]       = acc[m][nt][2] + be0;
            ob[(long long)(h0 + 1) * C_DIM + row + 8] = acc[m][nt][3] + be1;
        }
    }
}

extern "C" void kernel_launch(void* const* d_in, const int* in_sizes, int n_in,
                              void* d_out, int out_size) {
    // metadata order: x (unused), y, w, b
    const float* y    = (const float*)d_in[1];
    const float* w    = (const float*)d_in[2];
    const float* bias = (const float*)d_in[3];
    float* out        = (float*)d_out;

    dim3 grid(C_DIM / 128, 256);
    ar_mma_kernel<<<grid, 128, SMEM_BYTES>>>(y, w, bias, out);
}

// round 10
// speedup vs baseline: 1.2493x; 1.1875x over previous
#include <cuda_runtime.h>
#include <cuda_bf16.h>
#include <cstdint>

#define T_DIM    168
#define C_DIM    1024
#define NSEQ     168
#define HORIZON  24
#define KPAD     176                 // 11 k-steps of 16
#define KSTEPS   11
#define T_PER_CTA 4
#define QTOT     (T_PER_CTA * KSTEPS)        // 44 chunks per CTA
#define BSTRIDE_B ((long long)T_DIM * C_DIM * 4)   // bytes per b

// ---- smem layout ----
#define ROW_F       132              // floats per padded row (528 B)
#define STAGE_BYTES (16 * 528)       // 8448 per chunk buffer
#define NBUF        3
#define BFRAG_OFF   (NBUF * STAGE_BYTES)       // 25344
#define BFRAG_U32   (2 * KSTEPS * 3 * 64)      // 4224 u32 = 16896 B
#define SBETA_OFF   (BFRAG_OFF + BFRAG_U32 * 4)     // 42240
#define SMEM_BYTES  (SBETA_OFF + HORIZON * 4)       // 42336 (< 48K)
#define WSPAD_OFF   (2 * STAGE_BYTES)   // transient [199] fp32, dies pre-chunk2

// =================== PTX helpers ===================
__device__ __forceinline__ void cp16(uint32_t saddr, const void* gptr) {
    asm volatile("cp.async.cg.shared.global [%0], [%1], 16;"
                 :: "r"(saddr), "l"(gptr));
}
__device__ __forceinline__ void cp_commit() {
    asm volatile("cp.async.commit_group;");
}
template<int N>
__device__ __forceinline__ void cp_wait() {
    asm volatile("cp.async.wait_group %0;" :: "n"(N) : "memory");
}
__device__ __forceinline__ uint32_t cvt2(float hi, float lo) {
    uint32_t r;
    asm("cvt.rn.bf16x2.f32 %0, %1, %2;" : "=r"(r) : "f"(hi), "f"(lo));
    return r;
}
__device__ __forceinline__ void split_pair(float v0, float v1,
                                           uint32_t& hp, uint32_t& lp) {
    hp = cvt2(v1, v0);
    float h1 = __uint_as_float(hp & 0xffff0000u);
    float h0 = __uint_as_float(hp << 16);
    lp = cvt2(v1 - h1, v0 - h0);
}
__device__ __forceinline__ void mma16816(float* c, const uint32_t* a,
                                         const uint32_t* b) {
    asm volatile(
        "mma.sync.aligned.m16n8k16.row.col.f32.bf16.bf16.f32 "
        "{%0,%1,%2,%3}, {%4,%5,%6,%7}, {%8,%9}, {%0,%1,%2,%3};"
        : "+f"(c[0]), "+f"(c[1]), "+f"(c[2]), "+f"(c[3])
        : "r"(a[0]), "r"(a[1]), "r"(a[2]), "r"(a[3]), "r"(b[0]), "r"(b[1]));
}
__device__ __forceinline__ void lds_v2(uint32_t& r0, uint32_t& r1, uint32_t addr) {
    asm volatile("ld.shared.v2.u32 {%0,%1}, [%2];"
                 : "=r"(r0), "=r"(r1) : "r"(addr));
}

// =================== fused multi-b kernel ===================
// CTA = 128 channels x 4 consecutive b's (grid 8 x 64 = 512 CTAs, one wave).
// Phase 0 (once per CTA): AR recursion -> bf16 hi/lo mma fragments in SMEM.
// Phase 1: 44-chunk continuous cp.async stream; per-b epilogues overlap the
// next b's in-flight loads. Per-chunk math identical to the 35.7us R7 loop.
__global__ __launch_bounds__(128, 4)
void ar_mma_kernel(const float* __restrict__ y,
                   const float* __restrict__ w,
                   const float* __restrict__ bias,
                   float* __restrict__ out) {
    extern __shared__ char sm[];
    const int tid   = threadIdx.x;
    const int wid   = tid >> 5;
    const int lane  = tid & 31;
    const int lane4 = lane & 3;
    const int laneg = lane >> 2;
    const uint32_t sb = (uint32_t)__cvta_generic_to_shared((void*)sm);

    uint32_t* bf = (uint32_t*)(sm + BFRAG_OFF);
    float* sbeta = (float*)(sm + SBETA_OFF);
    float* wsp   = (float*)(sm + WSPAD_OFF);     // [199] zero-padded w

    const int b0  = blockIdx.y * T_PER_CTA;
    const int c0  = blockIdx.x * 128;
    const char* ytile0 = (const char*)(y + ((long long)b0 * T_DIM) * C_DIM + c0);

    // issue one chunk prefetch (16 y-rows -> padded 528B smem rows)
    auto issue_chunk = [&](const char* gsrc, int buf, int nrows) {
        const uint32_t sdst = sb + buf * STAGE_BYTES;
#pragma unroll
        for (int j = 0; j < 4; ++j) {
            int id  = j * 128 + tid;
            int row = id >> 5;
            int col = (id & 31) << 4;
            if (row < nrows)
                cp16(sdst + row * 528 + col, gsrc + (long long)row * 4096 + col);
        }
        cp_commit();
    };

    // ---- kick DRAM first: chunks (b0,0) and (b0,1) ----
    issue_chunk(ytile0, 0, 16);
    issue_chunk(ytile0 + 16 * 4096, 1, 16);

    // ---- ws_pad: w with 23 leading / 8 trailing zeros (guard-free reads) ----
    if (tid < 23) wsp[tid] = 0.f;
    if (tid < 8)  wsp[191 + tid] = 0.f;
    for (int i = tid; i < NSEQ; i += 128) wsp[23 + i] = w[i];
    __syncthreads();

    // ================= phase 0: recursion -> fragments (once) =================
    float wt[HORIZON];
#pragma unroll
    for (int j = 0; j < HORIZON; ++j) wt[j] = wsp[167 + j];   // w[144+j]

#pragma unroll
    for (int pass = 0; pass < 2; ++pass) {
        if (pass == 1 && tid >= 64) break;
        const int t  = tid + pass * 128;
        const bool wr = (t < KPAD) && ((t & 1) == 0);
        const int kt  = t >> 4;
        const int r   = (t >> 3) & 1;
        const int ln4 = (t & 7) >> 1;
        float col[HORIZON];
#pragma unroll
        for (int h = 0; h < HORIZON; ++h) {
            float acc = wsp[23 + t - h];                      // guard-free
#pragma unroll
            for (int j = 0; j < h; ++j) acc += wt[24 - h + j] * col[j];
            col[h] = acc;
            float v1 = __shfl_xor_sync(0xffffffffu, acc, 1);
            if (wr) {
                uint32_t hp, lp;
                split_pair(acc, v1, hp, lp);
                int base = (kt * 3 + (h >> 3)) * 64 + ((h & 7) * 4 + ln4) * 2 + r;
                bf[base] = hp;
                bf[KSTEPS * 3 * 64 + base] = lp;
            }
        }
    }
    if (tid == 127) {
        float bb[HORIZON];
        float bv = __ldg(&bias[0]);
#pragma unroll
        for (int h = 0; h < HORIZON; ++h) {
            float acc = bv;
#pragma unroll
            for (int j = 0; j < h; ++j) acc += wt[24 - h + j] * bb[j];
            bb[h] = acc;
            sbeta[h] = acc;
        }
    }
    __syncthreads();      // fragments + beta visible; ws_pad dead hereafter

    // ================= phase 1: 44-chunk continuous stream =================
    const int t0 = lane4 * 2;

    // rolling prefetch state: next chunk is (pb=0, pch=2) -> buffer 2
    const char* pg = ytile0 + 2 * 16 * 4096;
    int pch = 2, pb = 0, pbuf = 2;
    int cbuf = 0;
    int q = 0;

#pragma unroll 1
    for (int bi = 0; bi < T_PER_CTA; ++bi) {
        float acc[2][3][4];
#pragma unroll
        for (int m = 0; m < 2; ++m)
#pragma unroll
            for (int n = 0; n < 3; ++n)
#pragma unroll
                for (int rr = 0; rr < 4; ++rr) acc[m][n][rr] = 0.f;

#pragma unroll 1
        for (int kt = 0; kt < KSTEPS; ++kt, ++q) {
            if (q < QTOT - 1) { cp_wait<1>(); } else { cp_wait<0>(); }
            __syncthreads();

            if (q + 2 < QTOT) {
                issue_chunk(pg, pbuf, (pch == 10) ? 8 : 16);
                pbuf = (pbuf == 2) ? 0 : pbuf + 1;
                if (++pch == KSTEPS) {
                    pch = 0; ++pb;
                    pg = ytile0 + pb * BSTRIDE_B;
                } else {
                    pg += 16 * 4096;
                }
            }

            uint32_t Bh[3][2], Bl[3][2];
#pragma unroll
            for (int nt = 0; nt < 3; ++nt) {
                lds_v2(Bh[nt][0], Bh[nt][1],
                       sb + BFRAG_OFF + (uint32_t)(((0 * KSTEPS + kt) * 3 + nt) * 256 + lane * 8));
                lds_v2(Bl[nt][0], Bl[nt][1],
                       sb + BFRAG_OFF + (uint32_t)(((1 * KSTEPS + kt) * 3 + nt) * 256 + lane * 8));
            }

            const float* stg = (const float*)(sm + cbuf * STAGE_BYTES);
            cbuf = (cbuf == 2) ? 0 : cbuf + 1;
            const bool full = (kt < KSTEPS - 1);

#pragma unroll
            for (int m = 0; m < 2; ++m) {
                const int chI = wid * 32 + m * 16 + laneg;
                const float* p = stg + chI;

                float w00 = p[t0 * ROW_F],       w01 = p[(t0 + 1) * ROW_F];
                float w10 = p[t0 * ROW_F + 8],   w11 = p[(t0 + 1) * ROW_F + 8];

                uint32_t Ah[4], Al[4];
                split_pair(w00, w01, Ah[0], Al[0]);
                split_pair(w10, w11, Ah[1], Al[1]);
                if (full) {
                    float w02 = p[(t0 + 8) * ROW_F],     w03 = p[(t0 + 9) * ROW_F];
                    float w12 = p[(t0 + 8) * ROW_F + 8], w13 = p[(t0 + 9) * ROW_F + 8];
                    split_pair(w02, w03, Ah[2], Al[2]);
                    split_pair(w12, w13, Ah[3], Al[3]);
                } else {
                    Ah[2] = Ah[3] = Al[2] = Al[3] = 0u;   // t >= 168 contributes 0
                }

#pragma unroll
                for (int nt = 0; nt < 3; ++nt) {
                    mma16816(acc[m][nt], Ah, Bh[nt]);     // Ah*Bh
                    mma16816(acc[m][nt], Al, Bh[nt]);     // Al*Bh
                    mma16816(acc[m][nt], Ah, Bl[nt]);     // Ah*Bl
                }
            }
        }

        // ---- per-b epilogue (overlaps next b's in-flight chunks) ----
        float* ob = out + (long long)(b0 + bi) * HORIZON * C_DIM + c0;
#pragma unroll
        for (int nt = 0; nt < 3; ++nt) {
            const int h0 = nt * 8 + lane4 * 2;
            const float be0 = sbeta[h0];
            const float be1 = sbeta[h0 + 1];
#pragma unroll
            for (int m = 0; m < 2; ++m) {
                const int row = wid * 32 + m * 16 + laneg;
                ob[(long long)h0 * C_DIM + row]           = acc[m][nt][0] + be0;
                ob[(long long)(h0 + 1) * C_DIM + row]     = acc[m][nt][1] + be1;
                ob[(long long)h0 * C_DIM + row + 8]       = acc[m][nt][2] + be0;
                ob[(long long)(h0 + 1) * C_DIM + row + 8] = acc[m][nt][3] + be1;
            }
        }
    }
}

extern "C" void kernel_launch(void* const* d_in, const int* in_sizes, int n_in,
                              void* d_out, int out_size) {
    // metadata order: x (unused), y, w, b
    const float* y    = (const float*)d_in[1];
    const float* w    = (const float*)d_in[2];
    const float* bias = (const float*)d_in[3];
    float* out        = (float*)d_out;

    dim3 grid(C_DIM / 128, 256 / T_PER_CTA);
    ar_mma_kernel<<<grid, 128, SMEM_BYTES>>>(y, w, bias, out);
}